// round 2
// baseline (speedup 1.0000x reference)
#include <cuda_runtime.h>
#include <math.h>
#include <stdint.h>

// Problem constants
#define BATCH 2
#define SEQL  2048
#define HD    768
#define ED    1536
#define ND    16
#define RD    4
#define NLAYERS 8
#define TOK   (BATCH*SEQL)     // 4096 tokens
#define DBCW  36               // R + 2N

// ---------------- scratch (static device globals; no allocation) -------------
__device__ float g_hs  [TOK*HD];
__device__ float g_x   [TOK*HD];
__device__ float g_proj[TOK*2*ED];
__device__ float g_u   [TOK*ED];
__device__ float g_dbc [TOK*DBCW];
__device__ float g_dt  [TOK*ED];
__device__ float g_y   [TOK*ED];
__device__ float g_t1  [TOK*HD];
__device__ float g_t2  [TOK*HD];
__device__ float g_acc [TOK*HD];

// ---------------- math helpers ----------------
__device__ __forceinline__ float sigmoidf_(float x) {
    return 1.0f / (1.0f + __expf(-x));
}
__device__ __forceinline__ float siluf_(float x) {
    return x / (1.0f + __expf(-x));
}
__device__ __forceinline__ float softplusf_(float x) {
    if (x > 20.0f) return x;
    return __logf(1.0f + __expf(x));
}
__device__ __forceinline__ float ex2a(float x) {
    float r; asm("ex2.approx.ftz.f32 %0, %1;" : "=f"(r) : "f"(x)); return r;
}

// ---------------- embedding ----------------
__global__ void k_embed(const int* __restrict__ ids,
                        const float* __restrict__ tok,
                        const float* __restrict__ pos,
                        float* __restrict__ out) {
    int idx = blockIdx.x * blockDim.x + threadIdx.x;
    if (idx >= TOK*HD) return;
    int row = idx / HD;
    int h   = idx - row*HD;
    int l   = row & (SEQL-1);
    out[idx] = tok[ids[row]*HD + h] + pos[l*HD + h];
}

// ---------------- layernorm (one block per row of 768) ----------------
__global__ __launch_bounds__(256) void k_layernorm(const float* __restrict__ in,
                                                   float* __restrict__ out,
                                                   const float* __restrict__ w,
                                                   const float* __restrict__ b) {
    int row = blockIdx.x;
    const float* ip = in + (size_t)row * HD;
    int t = threadIdx.x;
    float v0 = ip[t], v1 = ip[t+256], v2 = ip[t+512];
    float s  = v0 + v1 + v2;
    float sq = v0*v0 + v1*v1 + v2*v2;
    #pragma unroll
    for (int o = 16; o > 0; o >>= 1) {
        s  += __shfl_down_sync(0xffffffffu, s, o);
        sq += __shfl_down_sync(0xffffffffu, sq, o);
    }
    __shared__ float sh[16];
    int wid = t >> 5, lane = t & 31;
    if (lane == 0) { sh[wid] = s; sh[8+wid] = sq; }
    __syncthreads();
    if (t == 0) {
        float S = 0.f, Q = 0.f;
        #pragma unroll
        for (int i = 0; i < 8; i++) { S += sh[i]; Q += sh[8+i]; }
        sh[0] = S; sh[8] = Q;
    }
    __syncthreads();
    float mean = sh[0] * (1.0f/HD);
    float var  = sh[8] * (1.0f/HD) - mean*mean;
    float rstd = rsqrtf(var + 1e-5f);
    float* op = out + (size_t)row * HD;
    op[t]     = (v0 - mean)*rstd*w[t]     + b[t];
    op[t+256] = (v1 - mean)*rstd*w[t+256] + b[t+256];
    op[t+512] = (v2 - mean)*rstd*w[t+512] + b[t+512];
}

// ---------------- SGEMM: C[M,N] = A[M,K] @ B[K,N] + bias (+epilogue) ---------
// MODE 0: +bias        MODE 1: +bias +res       MODE 2: silu(+bias)
// MODE 3: C += silu(+bias)
// Requires M%128==0, N%128==0, K%8==0
template<int MODE>
__global__ __launch_bounds__(256) void k_sgemm(int M, int N, int K,
                                               const float* __restrict__ A,
                                               const float* __restrict__ B,
                                               float* __restrict__ C,
                                               const float* __restrict__ bias,
                                               const float* __restrict__ res) {
    const int BM = 128, BN = 128, BK = 8;
    __shared__ float As[BK][BM];
    __shared__ float Bs[BK][BN];

    int tid = threadIdx.x;
    int tr = tid >> 4;         // 0..15
    int tc = tid & 15;         // 0..15
    int aRow = tid >> 1, aCol = (tid & 1) << 2;   // A tile 128x8, float4 per thread
    int bRow = tid >> 5, bCol = (tid & 31) << 2;  // B tile 8x128

    const float* Ag = A + (size_t)(blockIdx.y * BM) * K;
    const float* Bg = B + blockIdx.x * BN;

    float acc[8][8];
    #pragma unroll
    for (int m = 0; m < 8; m++)
        #pragma unroll
        for (int n = 0; n < 8; n++) acc[m][n] = 0.f;

    for (int k0 = 0; k0 < K; k0 += BK) {
        float4 av = *(const float4*)(Ag + (size_t)aRow*K + k0 + aCol);
        As[aCol+0][aRow] = av.x; As[aCol+1][aRow] = av.y;
        As[aCol+2][aRow] = av.z; As[aCol+3][aRow] = av.w;
        float4 bv = *(const float4*)(Bg + (size_t)(k0 + bRow)*N + bCol);
        *(float4*)&Bs[bRow][bCol] = bv;
        __syncthreads();
        #pragma unroll
        for (int kk = 0; kk < BK; kk++) {
            float4 a0 = *(const float4*)&As[kk][tr*8];
            float4 a1 = *(const float4*)&As[kk][tr*8+4];
            float4 b0 = *(const float4*)&Bs[kk][tc*8];
            float4 b1 = *(const float4*)&Bs[kk][tc*8+4];
            float ar[8] = {a0.x,a0.y,a0.z,a0.w,a1.x,a1.y,a1.z,a1.w};
            float br[8] = {b0.x,b0.y,b0.z,b0.w,b1.x,b1.y,b1.z,b1.w};
            #pragma unroll
            for (int m = 0; m < 8; m++)
                #pragma unroll
                for (int n = 0; n < 8; n++)
                    acc[m][n] += ar[m]*br[n];
        }
        __syncthreads();
    }

    int row0 = blockIdx.y*BM + tr*8;
    int col0 = blockIdx.x*BN + tc*8;
    float bv[8];
    #pragma unroll
    for (int n = 0; n < 8; n++) bv[n] = bias[col0+n];
    #pragma unroll
    for (int m = 0; m < 8; m++) {
        size_t base = (size_t)(row0+m)*N + col0;
        #pragma unroll
        for (int n = 0; n < 8; n++) {
            float v = acc[m][n] + bv[n];
            if (MODE == 1) v += res[base+n];
            if (MODE == 2) v = siluf_(v);
            if (MODE == 3) v = C[base+n] + siluf_(v);
            C[base+n] = v;
        }
    }
}

// ---------------- causal depthwise conv (K=4) + SiLU ----------------
__global__ void k_conv_silu(const float* __restrict__ proj,
                            const float* __restrict__ cw,
                            const float* __restrict__ cb,
                            float* __restrict__ u) {
    int idx = blockIdx.x * blockDim.x + threadIdx.x;
    if (idx >= TOK*ED) return;
    int e   = idx % ED;
    int row = idx / ED;
    int l   = row & (SEQL-1);
    float4 w = ((const float4*)cw)[e];   // cw[e*4 + 0..3]
    const float* xp = proj + (size_t)row*(2*ED) + e;
    float acc = cb[e] + w.w * xp[0];                 // j=3 -> l
    if (l >= 1) acc += w.z * xp[-(2*ED)];            // j=2 -> l-1
    if (l >= 2) acc += w.y * xp[-2*(2*ED)];          // j=1 -> l-2
    if (l >= 3) acc += w.x * xp[-3*(2*ED)];          // j=0 -> l-3
    u[idx] = siluf_(acc);
}

// ---------------- dbc = u @ xproj_w  (4096x1536 @ 1536x36) ----------------
__global__ __launch_bounds__(256) void k_gemm_dbc(const float* __restrict__ U,
                                                  const float* __restrict__ W,
                                                  float* __restrict__ out) {
    __shared__ float As[16][64];
    __shared__ float Bs[16][DBCW];
    int r0  = blockIdx.x * 64;
    int tid = threadIdx.x;
    int tr = tid >> 2;      // 0..63
    int tg = tid & 3;       // 0..3 (9 cols each)
    float acc[9];
    #pragma unroll
    for (int j = 0; j < 9; j++) acc[j] = 0.f;
    for (int k0 = 0; k0 < ED; k0 += 16) {
        float4 av = *(const float4*)(U + (size_t)(r0+tr)*ED + k0 + tg*4);
        As[tg*4+0][tr]=av.x; As[tg*4+1][tr]=av.y; As[tg*4+2][tr]=av.z; As[tg*4+3][tr]=av.w;
        for (int i = tid; i < 16*DBCW; i += 256) {
            int kk = i / DBCW, c = i - kk*DBCW;
            Bs[kk][c] = W[(size_t)(k0+kk)*DBCW + c];
        }
        __syncthreads();
        #pragma unroll
        for (int kk = 0; kk < 16; kk++) {
            float a = As[kk][tr];
            #pragma unroll
            for (int j = 0; j < 9; j++) acc[j] += a * Bs[kk][tg*9+j];
        }
        __syncthreads();
    }
    float* op = out + (size_t)(r0+tr)*DBCW + tg*9;
    #pragma unroll
    for (int j = 0; j < 9; j++) op[j] = acc[j];
}

// ---------------- dt = softplus(dbc[:, :4] @ dt_w + dt_b) ----------------
__global__ void k_dt(const float* __restrict__ dbc,
                     const float* __restrict__ dtw,
                     const float* __restrict__ dtb,
                     float* __restrict__ dt) {
    int idx = blockIdx.x * blockDim.x + threadIdx.x;
    if (idx >= TOK*ED) return;
    int e   = idx % ED;
    int row = idx / ED;
    const float* d = dbc + (size_t)row*DBCW;
    float v = dtb[e];
    v += d[0]*dtw[0*ED+e];
    v += d[1]*dtw[1*ED+e];
    v += d[2]*dtw[2*ED+e];
    v += d[3]*dtw[3*ED+e];
    dt[idx] = softplusf_(v);
}

// ---------------- selective scan (+ u*D, + sigmoid(gate) fused) -------------
// warp handles 2 channels: lanes 0-15 = states of e0, lanes 16-31 = states of e1
__global__ __launch_bounds__(256) void k_scan(const float* __restrict__ u,
                                              const float* __restrict__ dt,
                                              const float* __restrict__ dbc,
                                              const float* __restrict__ proj,
                                              const float* __restrict__ A_log,
                                              const float* __restrict__ Dv,
                                              float* __restrict__ y) {
    int gw   = (blockIdx.x * blockDim.x + threadIdx.x) >> 5;  // global warp 0..1535
    int lane = threadIdx.x & 31;
    int b   = gw / (ED/2);
    int p   = gw - b*(ED/2);
    int n   = lane & 15;
    int sub = lane >> 4;
    int e   = p*2 + sub;

    // A2 = A * log2(e) = -exp(A_log) * 1.4427
    float A2   = -__expf(A_log[e*ND + n]) * 1.44269504088896f;
    float Dval = Dv[e];
    float h = 0.f;

    size_t rb = (size_t)b * SEQL;
    const float* up  = u    + rb*ED + e;
    const float* dtp = dt   + rb*ED + e;
    const float* gp  = proj + rb*(2*ED) + ED + e;
    const float* bp  = dbc  + rb*DBCW + RD + n;
    const float* cp  = bp + ND;
    float*       yp  = y    + rb*ED + e;

    #pragma unroll 2
    for (int t = 0; t < SEQL; t++) {
        float dtv = __ldg(dtp);
        float uv  = __ldg(up);
        float Bn  = __ldg(bp);
        float Cn  = __ldg(cp);
        float dA  = ex2a(dtv * A2);          // exp(dt*A), dt*A <= 0
        h = h*dA + (dtv*uv)*Bn;
        float part = h*Cn;
        part += __shfl_down_sync(0xffffffffu, part, 8, 16);
        part += __shfl_down_sync(0xffffffffu, part, 4, 16);
        part += __shfl_down_sync(0xffffffffu, part, 2, 16);
        part += __shfl_down_sync(0xffffffffu, part, 1, 16);
        if (n == 0) {
            float g = __ldg(gp);
            *yp = sigmoidf_(g) * (part + uv*Dval);
        }
        dtp += ED; up += ED; gp += 2*ED; bp += DBCW; cp += DBCW; yp += ED;
    }
}

// ---------------- fractal final: hs += acc * (0.5/3) ----------------
__global__ void k_frac_add(float* __restrict__ hs, const float* __restrict__ acc) {
    int idx = blockIdx.x * blockDim.x + threadIdx.x;
    if (idx >= TOK*HD) return;
    hs[idx] += acc[idx] * (0.5f/3.0f);
}

// ---------------- host launcher ----------------
extern "C" void kernel_launch(void* const* d_in, const int* in_sizes, int n_in,
                              void* d_out, int out_size) {
    const int*   ids     = (const int*)  d_in[0];
    const float* tok     = (const float*)d_in[1];
    const float* pos     = (const float*)d_in[2];
    const float* ln_w    = (const float*)d_in[3];
    const float* ln_b    = (const float*)d_in[4];
    const float* in_w    = (const float*)d_in[5];
    const float* in_b    = (const float*)d_in[6];
    const float* conv_w  = (const float*)d_in[7];
    const float* conv_b  = (const float*)d_in[8];
    const float* xproj_w = (const float*)d_in[9];
    const float* dt_w    = (const float*)d_in[10];
    const float* dt_b    = (const float*)d_in[11];
    const float* A_log   = (const float*)d_in[12];
    const float* Dv      = (const float*)d_in[13];
    const float* out_w   = (const float*)d_in[14];
    const float* out_b   = (const float*)d_in[15];
    const float* frac_w  = (const float*)d_in[16];
    const float* frac_b  = (const float*)d_in[17];
    const float* fln_w   = (const float*)d_in[18];
    const float* fln_b   = (const float*)d_in[19];

    float *hs,*x,*proj,*u,*dbc,*dt,*y,*t1,*t2,*acc;
    cudaGetSymbolAddress((void**)&hs,   g_hs);
    cudaGetSymbolAddress((void**)&x,    g_x);
    cudaGetSymbolAddress((void**)&proj, g_proj);
    cudaGetSymbolAddress((void**)&u,    g_u);
    cudaGetSymbolAddress((void**)&dbc,  g_dbc);
    cudaGetSymbolAddress((void**)&dt,   g_dt);
    cudaGetSymbolAddress((void**)&y,    g_y);
    cudaGetSymbolAddress((void**)&t1,   g_t1);
    cudaGetSymbolAddress((void**)&t2,   g_t2);
    cudaGetSymbolAddress((void**)&acc,  g_acc);

    k_embed<<<(TOK*HD + 255)/256, 256>>>(ids, tok, pos, hs);

    for (int l = 0; l < NLAYERS; l++) {
        const float* lw   = ln_w   + (size_t)l*HD;
        const float* lb   = ln_b   + (size_t)l*HD;
        const float* iw   = in_w   + (size_t)l*HD*2*ED;
        const float* ib   = in_b   + (size_t)l*2*ED;
        const float* cw   = conv_w + (size_t)l*ED*4;
        const float* cb   = conv_b + (size_t)l*ED;
        const float* xw   = xproj_w+ (size_t)l*ED*DBCW;
        const float* dwp  = dt_w   + (size_t)l*RD*ED;
        const float* dbp  = dt_b   + (size_t)l*ED;
        const float* Al   = A_log  + (size_t)l*ED*ND;
        const float* Dl   = Dv     + (size_t)l*ED;
        const float* ow   = out_w  + (size_t)l*ED*HD;
        const float* ob   = out_b  + (size_t)l*HD;

        k_layernorm<<<TOK, 256>>>(hs, x, lw, lb);

        // proj = x @ in_w + in_b    [4096 x 3072], K=768
        k_sgemm<0><<<dim3(2*ED/128, TOK/128), 256>>>(TOK, 2*ED, HD, x, iw, proj, ib, nullptr);

        k_conv_silu<<<(TOK*ED)/256, 256>>>(proj, cw, cb, u);

        k_gemm_dbc<<<TOK/64, 256>>>(u, xw, dbc);

        k_dt<<<(TOK*ED)/256, 256>>>(dbc, dwp, dbp, dt);

        k_scan<<<(BATCH*(ED/2)*32)/256, 256>>>(u, dt, dbc, proj, Al, Dl, y);

        // hs = y @ out_w + out_b + hs   [4096 x 768], K=1536
        k_sgemm<1><<<dim3(HD/128, TOK/128), 256>>>(TOK, HD, ED, y, ow, hs, ob, hs);

        // fractal tail: 3 chains of 3 silu-GEMMs, accumulate into acc
        for (int i = 0; i < 3; i++) {
            const float* W  = frac_w + ((size_t)l*3 + i)*HD*HD;
            const float* fb = frac_b + ((size_t)l*3 + i)*HD;
            k_sgemm<2><<<dim3(HD/128, TOK/128), 256>>>(TOK, HD, HD, hs, W, t1, fb, nullptr);
            k_sgemm<2><<<dim3(HD/128, TOK/128), 256>>>(TOK, HD, HD, t1, W, t2, fb, nullptr);
            if (i == 0)
                k_sgemm<2><<<dim3(HD/128, TOK/128), 256>>>(TOK, HD, HD, t2, W, acc, fb, nullptr);
            else
                k_sgemm<3><<<dim3(HD/128, TOK/128), 256>>>(TOK, HD, HD, t2, W, acc, fb, nullptr);
        }
        k_frac_add<<<(TOK*HD)/256, 256>>>(hs, acc);
    }

    k_layernorm<<<TOK, 256>>>(hs, (float*)d_out, fln_w, fln_b);
}